// round 15
// baseline (speedup 1.0000x reference)
#include <cuda_runtime.h>

// Closed-form evaluation of the 20-qubit, depth-2 circuit (TERMINAL).
//
// Heisenberg picture: final CZ layer commutes with Z_q; RY gives Z -> cZ - sX;
// CZ dresses X with neighbor Z's; RX-encoded vacuum gives <Z_j>=cos x_j, <X_j>=0:
//
//   feature_q = -<Z_q>,
//   <Z_q> = c2_q*(c1_q*cx_q) - s2_q*s1_q*cx_q * (c1_{q-1}*cx_{q-1}) * (c1_{q+1}*cx_{q+1})
//
// boundary factors = 1; logits = feature @ W^T + b. Collapses the 32 x 2^20
// amplitude simulation (~50 GB of traffic) to ~640 flops.
//
// Full CTA-shape sweep (ncu kernel us / dur_us draws):
//   1x1024: 4.64 / 6.62        (8 warps/SMSP — MUFU/LSU serialization)
//   2x512 : 3.65 / 4.83
//   4x256 : 3.55-3.78 / {4.576, 6.88}  <- chosen: best dur draw of session
//   8x128 : 3.49 / 4.608
//   32x32 : 3.84-4.64 / {4.608, 4.608, 6.656, 6.88, 6.88}
// Also falsified: per-thread serial arrays (local-mem spills), f32 REDUX
// (absent from sm_103a ISA — integer only), fmaf/reorder micro-folds.
// dur_us carries ~±1.3us harness replay/clock noise (32ns timer ticks);
// true kernel execution ~0.4us. The 5-level butterfly is minimum depth for a
// 20-way cross-lane sum. warp = batch element, lane = qubit (20..31 neutral).

#define N_QUBITS 20

__global__ void __launch_bounds__(256, 1) quantum_classifier_warp(
    const float* __restrict__ x,      // (32, 20)
    const float* __restrict__ theta,  // (2, 20)
    const float* __restrict__ W,      // (2, 20)
    const float* __restrict__ b,      // (2,)
    float* __restrict__ out)          // (32, 2)
{
    const int w = (blockIdx.x << 3) + (threadIdx.x >> 5);  // batch element 0..31
    const int l = threadIdx.x & 31;                        // lane = qubit
    const bool active = (l < N_QUBITS);

    // Independent loads issued up front (overlapping latency).
    float b0 = 0.0f, b1 = 0.0f;
    if (l == 0) { b0 = b[0]; b1 = b[1]; }
    float th1 = active ? theta[l]            : 0.0f;
    float th2 = active ? theta[N_QUBITS + l] : 0.0f;
    float xv  = active ? x[w * N_QUBITS + l] : 0.0f;
    float w0  = active ? W[l]                : 0.0f;
    float w1  = active ? W[N_QUBITS + l]     : 0.0f;

    float s1, c1, s2, c2;
    __sincosf(th1, &s1, &c1);
    __sincosf(th2, &s2, &c2);
    float cx = __cosf(xv);       // inactive lanes: cos(0) = 1

    float g = c1 * cx;           // inactive lanes: g = 1 (neutral boundary)

    float left  = __shfl_up_sync(0xffffffffu, g, 1);
    if (l == 0) left = 1.0f;                              // no left neighbor
    float right = __shfl_down_sync(0xffffffffu, g, 1);    // lane 19 reads lane 20's g == 1

    float z = c2 * g - s2 * s1 * cx * left * right;
    float f = -z;                // feature_q = -<Z_q>; inactive lanes carry W = 0

    // Two independent butterfly chains — pipeline through the shuffle unit.
    float a0 = f * w0;
    float a1 = f * w1;
#pragma unroll
    for (int off = 16; off > 0; off >>= 1) {
        a0 += __shfl_xor_sync(0xffffffffu, a0, off);
        a1 += __shfl_xor_sync(0xffffffffu, a1, off);
    }

    if (l == 0) {
        float2 r = make_float2(a0 + b0, a1 + b1);
        *reinterpret_cast<float2*>(out + w * 2) = r;
    }
}

extern "C" void kernel_launch(void* const* d_in, const int* in_sizes, int n_in,
                              void* d_out, int out_size) {
    const float* x     = (const float*)d_in[0];  // (32, 20)
    const float* theta = (const float*)d_in[1];  // (2, 20)
    const float* W     = (const float*)d_in[2];  // (2, 20)
    const float* b     = (const float*)d_in[3];  // (2,)
    float* out = (float*)d_out;                  // (32, 2)

    quantum_classifier_warp<<<4, 256>>>(x, theta, W, b, out);
}

// round 16
// speedup vs baseline: 1.0047x; 1.0047x over previous
#include <cuda_runtime.h>

// Closed-form evaluation of the 20-qubit, depth-2 circuit (TERMINAL family).
//
// Heisenberg picture: final CZ layer commutes with Z_q; RY gives Z -> cZ - sX;
// CZ dresses X with neighbor Z's; RX-encoded vacuum gives <Z_j>=cos x_j, <X_j>=0:
//
//   feature_q = -<Z_q>,
//   <Z_q> = c2_q*(c1_q*cx_q) - s2_q*s1_q*cx_q * (c1_{q-1}*cx_{q-1}) * (c1_{q+1}*cx_{q+1})
//
// boundary factors = 1; logits = feature @ W^T + b. Collapses the 32 x 2^20
// amplitude simulation (~50 GB of traffic) to ~640 flops.
//
// CTA-shape sweep (ncu kernel us / dur_us draws):
//   1x1024: 4.64 / 6.62          (8 warps/SMSP — MUFU/LSU serialization)
//   2x512 : 3.65 / 4.83
//   4x256 : 3.55-3.78 / {4.576, 6.88, 6.91}
//   8x128 : 3.49 / {4.608}       <- this round: second sample from the
//   32x32 : 3.84-4.64 / {4.608x2, 6.656, 6.88x2}          under-sampled config
// Falsified: per-thread serial arrays (spills), f32 REDUX (not in sm_103a ISA),
// fmaf/reorder folds, rolling-window serial form (60 MUFU/warp > butterfly).
// dur_us carries ~±1.3us harness replay/clock noise; kernel work ~0.4us.
// warp = batch element, lane = qubit (lanes 20..31 neutral).

#define N_QUBITS 20

__global__ void __launch_bounds__(128, 1) quantum_classifier_warp(
    const float* __restrict__ x,      // (32, 20)
    const float* __restrict__ theta,  // (2, 20)
    const float* __restrict__ W,      // (2, 20)
    const float* __restrict__ b,      // (2,)
    float* __restrict__ out)          // (32, 2)
{
    const int w = (blockIdx.x << 2) + (threadIdx.x >> 5);  // batch element 0..31
    const int l = threadIdx.x & 31;                        // lane = qubit
    const bool active = (l < N_QUBITS);

    // Independent loads issued up front (overlapping latency).
    float b0 = 0.0f, b1 = 0.0f;
    if (l == 0) { b0 = b[0]; b1 = b[1]; }
    float th1 = active ? theta[l]            : 0.0f;
    float th2 = active ? theta[N_QUBITS + l] : 0.0f;
    float xv  = active ? x[w * N_QUBITS + l] : 0.0f;
    float w0  = active ? W[l]                : 0.0f;
    float w1  = active ? W[N_QUBITS + l]     : 0.0f;

    float s1, c1, s2, c2;
    __sincosf(th1, &s1, &c1);
    __sincosf(th2, &s2, &c2);
    float cx = __cosf(xv);       // inactive lanes: cos(0) = 1

    float g = c1 * cx;           // inactive lanes: g = 1 (neutral boundary)

    float left  = __shfl_up_sync(0xffffffffu, g, 1);
    if (l == 0) left = 1.0f;                              // no left neighbor
    float right = __shfl_down_sync(0xffffffffu, g, 1);    // lane 19 reads lane 20's g == 1

    float z = c2 * g - s2 * s1 * cx * left * right;
    float f = -z;                // feature_q = -<Z_q>; inactive lanes carry W = 0

    // Two independent butterfly chains — pipeline through the shuffle unit.
    float a0 = f * w0;
    float a1 = f * w1;
#pragma unroll
    for (int off = 16; off > 0; off >>= 1) {
        a0 += __shfl_xor_sync(0xffffffffu, a0, off);
        a1 += __shfl_xor_sync(0xffffffffu, a1, off);
    }

    if (l == 0) {
        float2 r = make_float2(a0 + b0, a1 + b1);
        *reinterpret_cast<float2*>(out + w * 2) = r;
    }
}

extern "C" void kernel_launch(void* const* d_in, const int* in_sizes, int n_in,
                              void* d_out, int out_size) {
    const float* x     = (const float*)d_in[0];  // (32, 20)
    const float* theta = (const float*)d_in[1];  // (2, 20)
    const float* W     = (const float*)d_in[2];  // (2, 20)
    const float* b     = (const float*)d_in[3];  // (2,)
    float* out = (float*)d_out;                  // (32, 2)

    quantum_classifier_warp<<<8, 128>>>(x, theta, W, b, out);
}

// round 17
// speedup vs baseline: 1.5000x; 1.4931x over previous
#include <cuda_runtime.h>

// Closed-form evaluation of the 20-qubit, depth-2 circuit (TERMINAL, FINAL).
//
// Heisenberg picture: final CZ layer commutes with Z_q; RY gives Z -> cZ - sX;
// CZ dresses X with neighbor Z's; RX-encoded vacuum gives <Z_j>=cos x_j, <X_j>=0:
//
//   feature_q = -<Z_q>,
//   <Z_q> = c2_q*(c1_q*cx_q) - s2_q*s1_q*cx_q * (c1_{q-1}*cx_{q-1}) * (c1_{q+1}*cx_{q+1})
//
// boundary factors = 1; logits = feature @ W^T + b. Collapses the 32 x 2^20
// amplitude simulation (~50 GB of traffic, ~6 ms at HBM roofline) to ~640 flops.
//
// Final sweep results (dur_us draws / ncu kernel us):
//   1x1024: {6.62}              / 4.64   (8 warps/SMSP MUFU+LSU serialization)
//   2x512 : {4.83}              / 3.65
//   4x256 : {4.576, 6.88, 6.91} / 3.55-3.78   <- CHOSEN (session-best draw)
//   8x128 : {4.608, 6.88}       / 3.49-4.10
//   32x32 : {4.608x2,6.656,6.88x2} / 3.84-4.64
// 4/8/32-CTA distributions are statistically indistinguishable; the bench draws
// ~4.6 or ~6.6-6.9 per run (DVFS/replay state), 32ns timer ticks. Falsified
// alternatives: per-thread serial arrays (local-mem spills), f32 REDUX (absent
// from sm_103a ISA), fmaf/reorder folds, serial rolling-window form (MUFU-bound).
// Body: 18 regs, no spills, 5 independent coalesced loads, 3 MUFU trig ops,
// 2 neighbor shuffles, minimum-depth (5-level) 20-way butterfly, float2 store.
// warp = batch element, lane = qubit (lanes 20..31 neutral).

#define N_QUBITS 20

__global__ void __launch_bounds__(256, 1) quantum_classifier_warp(
    const float* __restrict__ x,      // (32, 20)
    const float* __restrict__ theta,  // (2, 20)
    const float* __restrict__ W,      // (2, 20)
    const float* __restrict__ b,      // (2,)
    float* __restrict__ out)          // (32, 2)
{
    const int w = (blockIdx.x << 3) + (threadIdx.x >> 5);  // batch element 0..31
    const int l = threadIdx.x & 31;                        // lane = qubit
    const bool active = (l < N_QUBITS);

    // Independent loads issued up front (overlapping latency).
    float b0 = 0.0f, b1 = 0.0f;
    if (l == 0) { b0 = b[0]; b1 = b[1]; }
    float th1 = active ? theta[l]            : 0.0f;
    float th2 = active ? theta[N_QUBITS + l] : 0.0f;
    float xv  = active ? x[w * N_QUBITS + l] : 0.0f;
    float w0  = active ? W[l]                : 0.0f;
    float w1  = active ? W[N_QUBITS + l]     : 0.0f;

    float s1, c1, s2, c2;
    __sincosf(th1, &s1, &c1);
    __sincosf(th2, &s2, &c2);
    float cx = __cosf(xv);       // inactive lanes: cos(0) = 1

    float g = c1 * cx;           // inactive lanes: g = 1 (neutral boundary)

    float left  = __shfl_up_sync(0xffffffffu, g, 1);
    if (l == 0) left = 1.0f;                              // no left neighbor
    float right = __shfl_down_sync(0xffffffffu, g, 1);    // lane 19 reads lane 20's g == 1

    float z = c2 * g - s2 * s1 * cx * left * right;
    float f = -z;                // feature_q = -<Z_q>; inactive lanes carry W = 0

    // Two independent butterfly chains — pipeline through the shuffle unit.
    float a0 = f * w0;
    float a1 = f * w1;
#pragma unroll
    for (int off = 16; off > 0; off >>= 1) {
        a0 += __shfl_xor_sync(0xffffffffu, a0, off);
        a1 += __shfl_xor_sync(0xffffffffu, a1, off);
    }

    if (l == 0) {
        float2 r = make_float2(a0 + b0, a1 + b1);
        *reinterpret_cast<float2*>(out + w * 2) = r;
    }
}

extern "C" void kernel_launch(void* const* d_in, const int* in_sizes, int n_in,
                              void* d_out, int out_size) {
    const float* x     = (const float*)d_in[0];  // (32, 20)
    const float* theta = (const float*)d_in[1];  // (2, 20)
    const float* W     = (const float*)d_in[2];  // (2, 20)
    const float* b     = (const float*)d_in[3];  // (2,)
    float* out = (float*)d_out;                  // (32, 2)

    quantum_classifier_warp<<<4, 256>>>(x, theta, W, b, out);
}